// round 6
// baseline (speedup 1.0000x reference)
#include <cuda_runtime.h>

#define NQ  10
#define DIM 1024
#define NL  4
#define TPB 128

typedef unsigned long long u64;

__device__ u64 g_gmat[NL * NQ][8];       // packed gate coefficients
__device__ unsigned g_T[2][DIM / 2];     // swizzled gather word-table
__device__ unsigned g_cst[2][32];        // pass-2 store addr constants k*32 + A·k

__device__ __forceinline__ u64 pack2(float x, float y) {
    u64 r; asm("mov.b64 %0, {%1,%2};" : "=l"(r) : "f"(x), "f"(y)); return r;
}
__device__ __forceinline__ void unpk(u64 v, float& x, float& y) {
    asm("mov.b64 {%0,%1}, %2;" : "=f"(x), "=f"(y) : "l"(v));
}
__device__ __forceinline__ u64 swp(u64 v) {
    u64 r;
    asm("{\n\t.reg .b32 lo, hi;\n\tmov.b64 {lo,hi}, %1;\n\tmov.b64 %0, {hi,lo};\n\t}"
        : "=l"(r) : "l"(v));
    return r;
}
__device__ __forceinline__ u64 ffma2(u64 a, u64 b, u64 c) {
    u64 d; asm("fma.rn.f32x2 %0, %1, %2, %3;" : "=l"(d) : "l"(a), "l"(b), "l"(c)); return d;
}
__device__ __forceinline__ u64 fmul2(u64 a, u64 b) {
    u64 d; asm("mul.rn.f32x2 %0, %1, %2;" : "=l"(d) : "l"(a), "l"(b)); return d;
}
__device__ __forceinline__ u64 fadd2(u64 a, u64 b) {
    u64 d; asm("add.rn.f32x2 %0, %1, %2;" : "=l"(d) : "l"(a), "l"(b)); return d;
}
__device__ __forceinline__ float2 cmulf(float2 a, float2 b) {
    return make_float2(a.x * b.x - a.y * b.y, a.x * b.y + a.y * b.x);
}

// ---- GF(2) helpers (precompute only) ----
__device__ __forceinline__ unsigned finv10(int type, unsigned idx) {
    int off = type ? (NQ / 2) : 1;
    unsigned y = idx;
    #pragma unroll
    for (int i = NQ - 1; i >= 0; --i) {
        int bc = NQ - 1 - i;
        int bt = NQ - 1 - ((i + off) % NQ);
        y ^= ((y >> bc) & 1u) << bt;
    }
    return y;
}
__device__ __forceinline__ unsigned gf2_mv(const unsigned* cols, unsigned x) {
    unsigned r = 0;
    #pragma unroll
    for (int i = 0; i < 5; ++i) if ((x >> i) & 1) r ^= cols[i];
    return r;
}
__device__ bool gf2_inv5(const unsigned* c) {
    unsigned m[5]; unsigned used = 0;
    #pragma unroll
    for (int i = 0; i < 5; ++i) m[i] = c[i];
    for (int bit = 0; bit < 5; ++bit) {
        int piv = -1;
        for (int i = 0; i < 5; ++i)
            if (!((used >> i) & 1) && ((m[i] >> bit) & 1)) { piv = i; break; }
        if (piv < 0) return false;
        used |= 1u << piv;
        for (int i = 0; i < 5; ++i)
            if (i != piv && ((m[i] >> bit) & 1)) m[i] ^= m[piv];
    }
    return true;
}

__global__ void precompute_kernel(const float* __restrict__ w) {
    __shared__ int sel[2];
    __shared__ unsigned Acols[2][5];
    int t = threadIdx.x;
    if (t < 2) sel[t] = 0x7FFFFFFF;

    // fused variational gates, standard packed layout
    if (t < NL * NQ) {
        float w0 = w[t * 3 + 0], w1 = w[t * 3 + 1], w2 = w[t * 3 + 2];
        float sb, cb; sincosf(0.5f * w1, &sb, &cb);
        float sp, cp; sincosf(0.5f * (w0 + w2), &sp, &cp);
        float sd, cd; sincosf(0.5f * (w0 - w2), &sd, &cd);
        float ar = cb * cp, ai = -cb * sp;     // U00
        float br = sb * cd, bi = -sb * sd;     // U10 ; U01=-conj(U10), U11=conj(U00)
        u64* g = g_gmat[t];
        g[0] = pack2(ar, ar);   g[1] = pack2(-ai, ai);     // c00,d00
        g[2] = pack2(-br, -br); g[3] = pack2(-bi, bi);     // c01,d01
        g[4] = pack2(br, br);   g[5] = pack2(-bi, bi);     // c10,d10
        g[6] = pack2(ar, ar);   g[7] = pack2(ai, -ai);     // c11,d11
    }
    __syncthreads();

    // search per-parity linear swizzle A with (R ^ A*P) invertible
    {
        int p = t >> 6, tn = t & 63;
        unsigned Pc[5], Rc[5];
        #pragma unroll
        for (int b = 0; b < 5; ++b) {
            unsigned y = finv10(p, 1u << (5 + b));
            Pc[b] = y >> 5; Rc[b] = y & 31u;
        }
        for (int trial = 0; trial < 8; ++trial) {
            int id = tn * 8 + trial;
            unsigned seed = (unsigned)id * 0x9E3779B9u + (unsigned)p * 0x85EBCA6Bu + 0x12345u;
            unsigned Ac[5];
            #pragma unroll
            for (int i = 0; i < 5; ++i) {
                seed = seed * 1664525u + 1013904223u;
                Ac[i] = (seed >> 13) & 31u;
            }
            unsigned Bc[5];
            #pragma unroll
            for (int b = 0; b < 5; ++b) Bc[b] = Rc[b] ^ gf2_mv(Ac, Pc[b]);
            if (gf2_inv5(Bc)) atomicMin(&sel[p], id);
        }
    }
    __syncthreads();
    if ((t & 63) == 0) {
        int p = t >> 6;
        int id = sel[p];
        unsigned Ac[5] = {0, 0, 0, 0, 0};
        if (id != 0x7FFFFFFF) {
            unsigned seed = (unsigned)id * 0x9E3779B9u + (unsigned)p * 0x85EBCA6Bu + 0x12345u;
            #pragma unroll
            for (int i = 0; i < 5; ++i) {
                seed = seed * 1664525u + 1013904223u;
                Ac[i] = (seed >> 13) & 31u;
            }
        }
        #pragma unroll
        for (int i = 0; i < 5; ++i) Acols[p][i] = Ac[i];
    }
    __syncthreads();

    // store-address constants
    if (t < 64) {
        int p = t >> 5, k = t & 31;
        g_cst[p][k] = (unsigned)(k * 32) + gf2_mv(Acols[p], (unsigned)k);
    }
    // gather word-table: word for (lane l, pair c) at l*16 + (c ^ (l&15) ^ (l>>4))
    for (int i = t; i < 2 * 512; i += blockDim.x) {
        int p = i >> 9, widx = i & 511;
        int l = widx >> 4, c = widx & 15;
        unsigned j0 = (unsigned)(l * 32 + 2 * c);
        unsigned y0 = finv10(p, j0);
        unsigned y1 = finv10(p, j0 + 1);
        unsigned e0 = (y0 >> 5) * 32 + ((y0 & 31u) ^ gf2_mv(Acols[p], y0 >> 5));
        unsigned e1 = (y1 >> 5) * 32 + ((y1 & 31u) ^ gf2_mv(Acols[p], y1 >> 5));
        g_T[p][l * 16 + (c ^ (l & 15) ^ (l >> 4))] = e0 | (e1 << 16);
    }
}

// gate on register-index bit mask M over 32 packed-complex amps
template<int M>
__device__ __forceinline__ void gate_reg(u64* r, const u64* __restrict__ C) {
    const u64 c00 = C[0], d00 = C[1], c01 = C[2], d01 = C[3];
    const u64 c10 = C[4], d10 = C[5], c11 = C[6], d11 = C[7];
    #pragma unroll
    for (int k = 0; k < 32; ++k) {
        if ((k & M) == 0) {
            const int k1 = k | M;
            u64 a0 = r[k], a1 = r[k1];
            u64 s0 = swp(a0), s1 = swp(a1);
            r[k]  = ffma2(c00, a0, ffma2(d00, s0, ffma2(c01, a1, fmul2(d01, s1))));
            r[k1] = ffma2(c10, a0, ffma2(d10, s0, ffma2(c11, a1, fmul2(d11, s1))));
        }
    }
}

__global__ __launch_bounds__(TPB, 5) void qsim_kernel(
    const float* __restrict__ x,     // (B, 2*NQ)
    float* __restrict__ out)         // (B, NQ)
{
    __shared__ u64 scratch[TPB / 32][DIM];     // 32 KB: per-warp state scratch
    __shared__ u64 gmat_s[NL * NQ][8];         // 2.5 KB
    __shared__ unsigned Tp_s[2][DIM / 2];      // 4 KB
    __shared__ unsigned cst_s[2][32];          // 256 B
    __shared__ float2 venc[TPB / 32][NQ][2];

    const int t    = threadIdx.x;
    const int lane = t & 31;
    const int wid  = t >> 5;
    const int s    = blockIdx.x * (TPB / 32) + wid;
    const float inv_sqrt2 = 0.70710678118654752440f;
    const float pi_f      = 3.14159265358979323846f;

    // copy precomputed tables
    {
        const u64* gs = &g_gmat[0][0];
        u64* gd = &gmat_s[0][0];
        for (int i = t; i < NL * NQ * 8; i += TPB) gd[i] = gs[i];
        const unsigned* ts = &g_T[0][0];
        unsigned* td = &Tp_s[0][0];
        for (int i = t; i < DIM; i += TPB) td[i] = ts[i];
        const unsigned* cs = &g_cst[0][0];
        unsigned* cd = &cst_s[0][0];
        if (t < 64) cd[t] = cs[t];
    }
    // per-sample encoding columns: v = RZ(phi)*RY(theta)*H |0>
    if (lane < NQ) {
        int q = lane;
        float th = 0.5f * pi_f * (x[s * 2 * NQ + q]      + 1.0f);
        float ph = 0.5f * pi_f * (x[s * 2 * NQ + NQ + q] + 1.0f);
        float st, ct; sincosf(0.5f * th, &st, &ct);
        float sh, ch; sincosf(0.5f * ph, &sh, &ch);
        float a = inv_sqrt2 * (ct - st);
        float b = inv_sqrt2 * (ct + st);
        venc[wid][q][0] = make_float2(a * ch, -a * sh);
        venc[wid][q][1] = make_float2(b * ch,  b * sh);
    }
    __syncthreads();

    // ---- build product state: layout A: j = lane*32 + k, qubit q <-> j bit (9-q) ----
    u64 r[32];
    {
        float2 L = venc[wid][0][(lane >> 4) & 1];
        L = cmulf(L, venc[wid][1][(lane >> 3) & 1]);
        L = cmulf(L, venc[wid][2][(lane >> 2) & 1]);
        L = cmulf(L, venc[wid][3][(lane >> 1) & 1]);
        L = cmulf(L, venc[wid][4][lane & 1]);
        float2 RH[4], RL[4];
        #pragma unroll
        for (int h = 0; h < 4; ++h) RH[h] = cmulf(venc[wid][5][(h >> 1) & 1], venc[wid][6][h & 1]);
        #pragma unroll
        for (int l = 0; l < 4; ++l) RL[l] = cmulf(venc[wid][7][(l >> 1) & 1],
                                                  cmulf(venc[wid][8][0], venc[wid][8][0]));
        // (rebuild RL correctly below; avoid stale values)
        #pragma unroll
        for (int l = 0; l < 4; ++l) RL[l] = cmulf(venc[wid][8][(l >> 1) & 1], venc[wid][9][l & 1]);
        #pragma unroll
        for (int k = 0; k < 32; ++k) {
            float2 a = cmulf(L, cmulf(venc[wid][7][(k >> 4) & 1],
                                      cmulf(RH[(k >> 2) & 3], RL[k & 3])));
            r[k] = pack2(a.x, a.y);
        }
    }
    // NOTE on mapping above: k bit4->qubit5, bit3->q6, bit2->q7, bit1->q8, bit0->q9.
    // RH covers (q5,q6) via bits (4,3)? -- recompute cleanly instead:
    {
        float2 L = venc[wid][0][(lane >> 4) & 1];
        L = cmulf(L, venc[wid][1][(lane >> 3) & 1]);
        L = cmulf(L, venc[wid][2][(lane >> 2) & 1]);
        L = cmulf(L, venc[wid][3][(lane >> 1) & 1]);
        L = cmulf(L, venc[wid][4][lane & 1]);
        float2 HI[4], LO2[4];
        #pragma unroll
        for (int h = 0; h < 4; ++h) HI[h] = cmulf(venc[wid][5][(h >> 1) & 1], venc[wid][6][h & 1]);
        #pragma unroll
        for (int l = 0; l < 4; ++l) LO2[l] = cmulf(venc[wid][8][(l >> 1) & 1], venc[wid][9][l & 1]);
        #pragma unroll
        for (int k = 0; k < 32; ++k) {
            float2 a = cmulf(L, cmulf(HI[(k >> 3) & 3],
                                      cmulf(venc[wid][7][(k >> 2) & 1], LO2[k & 3])));
            r[k] = pack2(a.x, a.y);
        }
    }

    u64* sc = scratch[wid];

    #pragma unroll 1
    for (int layer = 0; layer < NL; ++layer) {
        const u64 (*G)[8] = &gmat_s[layer * NQ];
        // layout A: k bits 4..0 = qubits 5..9
        gate_reg<16>(r, G[5]);
        gate_reg<8>(r, G[6]);
        gate_reg<4>(r, G[7]);
        gate_reg<2>(r, G[8]);
        gate_reg<1>(r, G[9]);
        // pass 1: transpose to layout B (swap hi/lo 5 bits), conflict-free swizzle
        #pragma unroll
        for (int k = 0; k < 32; ++k)
            sc[lane * 32 + (k ^ lane)] = r[k];
        __syncwarp();
        #pragma unroll
        for (int k = 0; k < 32; ++k)
            r[k] = sc[k * 32 + (lane ^ k)];
        __syncwarp();
        // layout B: k bits 4..0 = qubits 0..4
        gate_reg<16>(r, G[0]);
        gate_reg<8>(r, G[1]);
        gate_reg<4>(r, G[2]);
        gate_reg<2>(r, G[3]);
        gate_reg<1>(r, G[4]);
        // pass 2: A-swizzled store, CNOT-ring gather back to layout A
        const unsigned* cst = cst_s[layer & 1];
        #pragma unroll
        for (int k = 0; k < 32; ++k)
            sc[cst[k] ^ lane] = r[k];
        __syncwarp();
        const unsigned* T = Tp_s[layer & 1];
        #pragma unroll
        for (int c = 0; c < 16; ++c) {
            unsigned tw = T[lane * 16 + (c ^ (lane & 15) ^ (lane >> 4))];
            r[2 * c]     = sc[tw & 0xffffu];
            r[2 * c + 1] = sc[tw >> 16];
        }
        __syncwarp();
    }

    // ---- <Z_q> readout (layout A) ----
    u64 tot = 0, accP[5] = {0,0,0,0,0}, accN[5] = {0,0,0,0,0};
    #pragma unroll
    for (int k = 0; k < 32; ++k) {
        u64 sq = fmul2(r[k], r[k]);          // (re^2, im^2)
        tot = fadd2(tot, sq);
        #pragma unroll
        for (int b = 0; b < 5; ++b) {
            if ((k >> b) & 1) accN[b] = fadd2(accN[b], sq);
            else              accP[b] = fadd2(accP[b], sq);
        }
    }
    float zq[NQ];
    {
        float tl, th; unpk(tot, tl, th);
        float pr_tot = tl + th;
        zq[0] = ((lane >> 4) & 1) ? -pr_tot : pr_tot;
        zq[1] = ((lane >> 3) & 1) ? -pr_tot : pr_tot;
        zq[2] = ((lane >> 2) & 1) ? -pr_tot : pr_tot;
        zq[3] = ((lane >> 1) & 1) ? -pr_tot : pr_tot;
        zq[4] = (lane & 1)        ? -pr_tot : pr_tot;
        #pragma unroll
        for (int b = 0; b < 5; ++b) {        // k bit b <-> qubit 9-b
            float pl, ph, nl, nh;
            unpk(accP[b], pl, ph); unpk(accN[b], nl, nh);
            zq[9 - b] = (pl + ph) - (nl + nh);
        }
    }
    #pragma unroll
    for (int q = 0; q < NQ; ++q) {
        #pragma unroll
        for (int o = 16; o > 0; o >>= 1)
            zq[q] += __shfl_xor_sync(0xffffffffu, zq[q], o);
    }
    if (lane == 0) {
        #pragma unroll
        for (int q = 0; q < NQ; ++q)
            out[s * NQ + q] = zq[q];
    }
}

extern "C" void kernel_launch(void* const* d_in, const int* in_sizes, int n_in,
                              void* d_out, int out_size) {
    const float* x = (const float*)d_in[0];
    const float* w = (const float*)d_in[1];
    float* out = (float*)d_out;
    int B = in_sizes[0] / (2 * NQ);   // 4096 flattened samples
    precompute_kernel<<<1, 128>>>(w);
    qsim_kernel<<<B / (TPB / 32), TPB>>>(x, out);
}

// round 7
// speedup vs baseline: 1.4209x; 1.4209x over previous
#include <cuda_runtime.h>

#define NQ  10
#define DIM 1024
#define NL  4
#define TPB 64

typedef unsigned long long u64;

__device__ u64 g_gmat[NL * NQ][8];       // packed gate coefficients
__device__ unsigned g_T[2][512];         // gather word-table (conflict-free layout)
__device__ unsigned g_Amul[2][32];       // A·v lookup per layer parity

__device__ __forceinline__ u64 pack2(float x, float y) {
    u64 r; asm("mov.b64 %0, {%1,%2};" : "=l"(r) : "f"(x), "f"(y)); return r;
}
__device__ __forceinline__ void unpk(u64 v, float& x, float& y) {
    asm("mov.b64 {%0,%1}, %2;" : "=f"(x), "=f"(y) : "l"(v));
}
__device__ __forceinline__ u64 swp(u64 v) {
    u64 r;
    asm("{\n\t.reg .b32 lo, hi;\n\tmov.b64 {lo,hi}, %1;\n\tmov.b64 %0, {hi,lo};\n\t}"
        : "=l"(r) : "l"(v));
    return r;
}
__device__ __forceinline__ u64 ffma2(u64 a, u64 b, u64 c) {
    u64 d; asm("fma.rn.f32x2 %0, %1, %2, %3;" : "=l"(d) : "l"(a), "l"(b), "l"(c)); return d;
}
__device__ __forceinline__ u64 fmul2(u64 a, u64 b) {
    u64 d; asm("mul.rn.f32x2 %0, %1, %2;" : "=l"(d) : "l"(a), "l"(b)); return d;
}
__device__ __forceinline__ u64 fadd2(u64 a, u64 b) {
    u64 d; asm("add.rn.f32x2 %0, %1, %2;" : "=l"(d) : "l"(a), "l"(b)); return d;
}
__device__ __forceinline__ float2 cmulf(float2 a, float2 b) {
    return make_float2(a.x * b.x - a.y * b.y, a.x * b.y + a.y * b.x);
}

// ---- GF(2) helpers (precompute only) ----
__device__ __forceinline__ unsigned finv10(int type, unsigned idx) {
    int off = type ? (NQ / 2) : 1;
    unsigned y = idx;
    #pragma unroll
    for (int i = NQ - 1; i >= 0; --i) {
        int bc = NQ - 1 - i;
        int bt = NQ - 1 - ((i + off) % NQ);
        y ^= ((y >> bc) & 1u) << bt;
    }
    return y;
}
__device__ __forceinline__ unsigned gf2_mv(const unsigned* cols, unsigned x) {
    unsigned r = 0;
    #pragma unroll
    for (int i = 0; i < 5; ++i) if ((x >> i) & 1) r ^= cols[i];
    return r;
}
__device__ bool gf2_rank5(const unsigned* c) {
    unsigned m[5]; unsigned used = 0;
    #pragma unroll
    for (int i = 0; i < 5; ++i) m[i] = c[i];
    for (int bit = 0; bit < 5; ++bit) {
        int piv = -1;
        for (int i = 0; i < 5; ++i)
            if (!((used >> i) & 1) && ((m[i] >> bit) & 1)) { piv = i; break; }
        if (piv < 0) return false;
        used |= 1u << piv;
        for (int i = 0; i < 5; ++i)
            if (i != piv && ((m[i] >> bit) & 1)) m[i] ^= m[piv];
    }
    return true;
}
__device__ __forceinline__ void seed_to_A(int id, int p, unsigned* Ac) {
    unsigned seed = (unsigned)id * 0x9E3779B9u + (unsigned)p * 0x85EBCA6Bu + 0x6789u;
    #pragma unroll
    for (int i = 0; i < 5; ++i) {
        seed = seed * 1664525u + 1013904223u;
        Ac[i] = (seed >> 13) & 31u;
    }
}

__global__ void precompute_kernel(const float* __restrict__ w) {
    __shared__ int sel[2];
    __shared__ unsigned Acols[2][5];
    int t = threadIdx.x;
    if (t < 2) sel[t] = 0x7FFFFFFF;

    // fused variational gates
    if (t < NL * NQ) {
        int q = t % NQ;
        float w0 = w[t * 3 + 0], w1 = w[t * 3 + 1], w2 = w[t * 3 + 2];
        float sb, cb; sincosf(0.5f * w1, &sb, &cb);
        float sp, cp; sincosf(0.5f * (w0 + w2), &sp, &cp);
        float sd, cd; sincosf(0.5f * (w0 - w2), &sd, &cd);
        float ar = cb * cp, ai = -cb * sp;   // U00
        float br = sb * cd, bi = -sb * sd;   // U10 ; U01=-conj(U10), U11=conj(U00)
        u64* g = g_gmat[t];
        if (q == 0) {
            // merged-gather layout: {c00,d00,c01,d01, c11,d11,c10,d10}
            g[0] = pack2(ar, ar);   g[1] = pack2(-ai, ai);
            g[2] = pack2(-br, -br); g[3] = pack2(-bi, bi);
            g[4] = pack2(ar, ar);   g[5] = pack2(ai, -ai);
            g[6] = pack2(br, br);   g[7] = pack2(-bi, bi);
        } else {
            // standard layout: {c00,d00,c01,d01,c10,d10,c11,d11}
            g[0] = pack2(ar, ar);   g[1] = pack2(-ai, ai);
            g[2] = pack2(-br, -br); g[3] = pack2(-bi, bi);
            g[4] = pack2(br, br);   g[5] = pack2(-bi, bi);
            g[6] = pack2(ar, ar);   g[7] = pack2(ai, -ai);
        }
    }
    __syncthreads();

    // search A per parity: store pass AND gather pass conflict-free
    {
        int p = t >> 6, tn = t & 63;
        unsigned Ph[5], Pl[5];
        #pragma unroll
        for (int i = 0; i < 5; ++i) {
            unsigned y = finv10(p, 1u << (4 + i));   // columns for j bits 4..8 (lane bits)
            Ph[i] = y >> 5; Pl[i] = y & 31u;
        }
        for (int trial = 0; trial < 8; ++trial) {
            int id = tn * 8 + trial;
            unsigned Ac[5]; seed_to_A(id, p, Ac);
            // constraint 1 (store): {0x10, A·e0..A·e3} rank 5
            unsigned B1[5] = {0x10u, Ac[0], Ac[1], Ac[2], Ac[3]};
            if (!gf2_rank5(B1)) continue;
            // constraint 2 (gather): bank cols for lane bits rank 5
            unsigned B2[5];
            #pragma unroll
            for (int i = 0; i < 5; ++i) B2[i] = Pl[i] ^ gf2_mv(Ac, Ph[i]);
            if (!gf2_rank5(B2)) continue;
            atomicMin(&sel[p], id);
        }
    }
    __syncthreads();
    if ((t & 63) == 0) {
        int p = t >> 6;
        unsigned Ac[5] = {0, 0, 0, 0, 0};
        if (sel[p] != 0x7FFFFFFF) seed_to_A(sel[p], p, Ac);
        #pragma unroll
        for (int i = 0; i < 5; ++i) Acols[p][i] = Ac[i];
    }
    __syncthreads();

    if (t < 64) {
        int p = t >> 5, v = t & 31;
        g_Amul[p][v] = gf2_mv(Acols[p], (unsigned)v);
    }
    // gather word-table: word for (W,lane,c) stored at W*256 + lane*8 + (c ^ (lane>>2))
    for (int i = t; i < 2 * 512; i += blockDim.x) {
        int p = i >> 9, widx = i & 511;
        int W = widx >> 8, lane = (widx >> 3) & 31, cs = widx & 7;
        int c = cs ^ (lane >> 2);
        unsigned j0 = (unsigned)(W * 512 + lane * 16 + 2 * c);
        unsigned e[2];
        #pragma unroll
        for (int h = 0; h < 2; ++h) {
            unsigned y = finv10(p, j0 + h);
            unsigned yh = y >> 5;
            unsigned addr = yh * 32 + ((y & 31u) ^ gf2_mv(Acols[p], yh));
            e[h] = addr | ((y >> 9) << 15);
        }
        g_T[p][widx] = e[0] | (e[1] << 16);
    }
}

// gate on k-bit mask M over 16 packed-complex amps
template<int M>
__device__ __forceinline__ void gate_reg(u64* r, const u64* __restrict__ C) {
    const u64 c00 = C[0], d00 = C[1], c01 = C[2], d01 = C[3];
    const u64 c10 = C[4], d10 = C[5], c11 = C[6], d11 = C[7];
    #pragma unroll
    for (int k = 0; k < 16; ++k) {
        if ((k & M) == 0) {
            const int k1 = k | M;
            u64 a0 = r[k], a1 = r[k1];
            u64 s0 = swp(a0), s1 = swp(a1);
            r[k]  = ffma2(c00, a0, ffma2(d00, s0, ffma2(c01, a1, fmul2(d01, s1))));
            r[k1] = ffma2(c10, a0, ffma2(d10, s0, ffma2(c11, a1, fmul2(d11, s1))));
        }
    }
}

// gate on lane-bit xor distance D
template<int D>
__device__ __forceinline__ void gate_shfl(u64* r, const u64* __restrict__ C, int lane) {
    const bool b = (lane & D) != 0;
    const u64 cA = b ? C[6] : C[0];
    const u64 dA = b ? C[7] : C[1];
    const u64 cB = b ? C[4] : C[2];
    const u64 dB = b ? C[5] : C[3];
    #pragma unroll
    for (int k = 0; k < 16; ++k) {
        u64 own = r[k];
        u64 par = __shfl_xor_sync(0xffffffffu, own, D);
        r[k] = ffma2(cA, own, ffma2(dA, swp(own), ffma2(cB, par, fmul2(dB, swp(par)))));
    }
}

__global__ __launch_bounds__(TPB, 12) void qsim_kernel(
    const float* __restrict__ x,     // (B, 2*NQ)
    float* __restrict__ out)         // (B, NQ)
{
    __shared__ u64 sc[DIM];                    // 8 KB state scratch (A-swizzled)
    __shared__ u64 gmat_s[NL * NQ][8];         // 2.5 KB
    __shared__ unsigned Tp_s[2][512];          // 4 KB
    __shared__ float2 venc[NQ][2];
    __shared__ float red[2][NQ];

    const int t    = threadIdx.x;
    const int lane = t & 31;
    const int w    = t >> 5;                   // warp half = qubit-0 bit (j9)
    const int s    = blockIdx.x;
    const float inv_sqrt2 = 0.70710678118654752440f;
    const float pi_f      = 3.14159265358979323846f;

    // copy precomputed tables to smem
    {
        const u64* src = &g_gmat[0][0];
        u64* dst = &gmat_s[0][0];
        for (int i = t; i < NL * NQ * 8; i += TPB) dst[i] = src[i];
        const unsigned* ts = &g_T[0][0];
        unsigned* td = &Tp_s[0][0];
        for (int i = t; i < 1024; i += TPB) td[i] = ts[i];
    }
    // per-thread address constants from A tables
    const unsigned jhi = (unsigned)(w * 16 + (lane >> 1));
    const unsigned addrC0 = (jhi << 5) | (((unsigned)(lane & 1) << 4) ^ g_Amul[0][jhi]);
    const unsigned addrC1 = (jhi << 5) | (((unsigned)(lane & 1) << 4) ^ g_Amul[1][jhi]);
    const unsigned pc0 = 0x200u ^ g_Amul[0][16];
    const unsigned pc1 = 0x200u ^ g_Amul[1][16];

    if (t < NQ) {
        int q = t;
        float th = 0.5f * pi_f * (x[s * 2 * NQ + q]      + 1.0f);
        float ph = 0.5f * pi_f * (x[s * 2 * NQ + NQ + q] + 1.0f);
        float st, ct; sincosf(0.5f * th, &st, &ct);
        float sh, ch; sincosf(0.5f * ph, &sh, &ch);
        float a = inv_sqrt2 * (ct - st);
        float b = inv_sqrt2 * (ct + st);
        venc[q][0] = make_float2(a * ch, -a * sh);
        venc[q][1] = make_float2(b * ch,  b * sh);
    }
    __syncthreads();

    // ---- build product state: j = w*512 + lane*16 + k ; qubit q <-> j bit (9-q) ----
    u64 r[16];
    {
        float2 L = venc[0][w];
        L = cmulf(L, venc[1][(lane >> 4) & 1]);
        L = cmulf(L, venc[2][(lane >> 3) & 1]);
        L = cmulf(L, venc[3][(lane >> 2) & 1]);
        L = cmulf(L, venc[4][(lane >> 1) & 1]);
        L = cmulf(L, venc[5][lane & 1]);
        float2 RH[4], RL[4];
        #pragma unroll
        for (int h = 0; h < 4; ++h) RH[h] = cmulf(venc[6][(h >> 1) & 1], venc[7][h & 1]);
        #pragma unroll
        for (int l = 0; l < 4; ++l) RL[l] = cmulf(venc[8][(l >> 1) & 1], venc[9][l & 1]);
        #pragma unroll
        for (int k = 0; k < 16; ++k) {
            float2 a = cmulf(L, cmulf(RH[k >> 2], RL[k & 3]));
            r[k] = pack2(a.x, a.y);
        }
    }

    #pragma unroll 1
    for (int layer = 0; layer < NL; ++layer) {
        const u64 (*G)[8] = &gmat_s[layer * NQ];
        const int par = layer & 1;
        // qubits 6..9 on k bits
        gate_reg<8>(r, G[6]);
        gate_reg<4>(r, G[7]);
        gate_reg<2>(r, G[8]);
        gate_reg<1>(r, G[9]);
        // qubits 1..5 on lane bits
        gate_shfl<16>(r, G[1], lane);
        gate_shfl<8>(r, G[2], lane);
        gate_shfl<4>(r, G[3], lane);
        gate_shfl<2>(r, G[4], lane);
        gate_shfl<1>(r, G[5], lane);
        // store state (A-swizzled, conflict-free)
        const unsigned addrC = par ? addrC1 : addrC0;
        #pragma unroll
        for (int k = 0; k < 16; ++k)
            sc[addrC ^ (unsigned)k] = r[k];
        __syncthreads();
        // gather = CNOT ring composed with qubit-0 gate (conflict-free loads)
        const unsigned PC = par ? pc1 : pc0;
        const u64 q0_0 = G[0][0], q0_1 = G[0][1], q0_2 = G[0][2], q0_3 = G[0][3];
        const u64 q1_0 = G[0][4], q1_1 = G[0][5], q1_2 = G[0][6], q1_3 = G[0][7];
        const unsigned tbase = ((unsigned)w << 8) | ((unsigned)lane << 3);
        #pragma unroll
        for (int c = 0; c < 8; ++c) {
            unsigned tw = Tp_s[par][tbase | ((unsigned)c ^ (unsigned)(lane >> 2))];
            #pragma unroll
            for (int h = 0; h < 2; ++h) {
                unsigned e = (h == 0) ? (tw & 0xffffu) : (tw >> 16);
                unsigned idx = e & 1023u;
                bool bb = (e >> 15) != 0;
                u64 a = sc[idx];
                u64 p = sc[idx ^ PC];
                u64 cA = bb ? q1_0 : q0_0;
                u64 dA = bb ? q1_1 : q0_1;
                u64 cB = bb ? q1_2 : q0_2;
                u64 dB = bb ? q1_3 : q0_3;
                r[2 * c + h] = ffma2(cA, a, ffma2(dA, swp(a), ffma2(cB, p, fmul2(dB, swp(p)))));
            }
        }
        __syncthreads();
    }

    // ---- <Z_q> readout ----
    u64 tot = 0, accP[4] = {0,0,0,0}, accN[4] = {0,0,0,0};
    #pragma unroll
    for (int k = 0; k < 16; ++k) {
        u64 sq = fmul2(r[k], r[k]);          // (re^2, im^2)
        tot = fadd2(tot, sq);
        #pragma unroll
        for (int b = 0; b < 4; ++b) {
            if ((k >> b) & 1) accN[b] = fadd2(accN[b], sq);
            else              accP[b] = fadd2(accP[b], sq);
        }
    }
    float zq[NQ];
    {
        float tl, th; unpk(tot, tl, th);
        float pr_tot = tl + th;
        zq[0] = w ? -pr_tot : pr_tot;
        zq[1] = (lane & 16) ? -pr_tot : pr_tot;
        zq[2] = (lane & 8)  ? -pr_tot : pr_tot;
        zq[3] = (lane & 4)  ? -pr_tot : pr_tot;
        zq[4] = (lane & 2)  ? -pr_tot : pr_tot;
        zq[5] = (lane & 1)  ? -pr_tot : pr_tot;
        #pragma unroll
        for (int b = 0; b < 4; ++b) {        // k bit b <-> qubit 9-b
            float pl, ph, nl, nh;
            unpk(accP[b], pl, ph); unpk(accN[b], nl, nh);
            zq[9 - b] = (pl + ph) - (nl + nh);
        }
    }
    #pragma unroll
    for (int q = 0; q < NQ; ++q) {
        #pragma unroll
        for (int o = 16; o > 0; o >>= 1)
            zq[q] += __shfl_xor_sync(0xffffffffu, zq[q], o);
    }
    if (lane == 0) {
        #pragma unroll
        for (int q = 0; q < NQ; ++q) red[w][q] = zq[q];
    }
    __syncthreads();
    if (t < NQ)
        out[s * NQ + t] = red[0][t] + red[1][t];
}

extern "C" void kernel_launch(void* const* d_in, const int* in_sizes, int n_in,
                              void* d_out, int out_size) {
    const float* x = (const float*)d_in[0];
    const float* w = (const float*)d_in[1];
    float* out = (float*)d_out;
    int B = in_sizes[0] / (2 * NQ);   // 4096 flattened samples
    precompute_kernel<<<1, 128>>>(w);
    qsim_kernel<<<B, TPB>>>(x, out);
}

// round 8
// speedup vs baseline: 1.4917x; 1.0499x over previous
#include <cuda_runtime.h>

#define NQ  10
#define DIM 1024
#define NL  4
#define TPB 64

typedef unsigned long long u64;

__device__ u64 g_gmat[NL * NQ][8];       // packed gate coefficients
__device__ unsigned g_T[2][512];         // gather word-table (conflict-free layout)
__device__ unsigned g_Amul[2][32];       // A·v lookup per layer parity

__device__ __forceinline__ u64 pack2(float x, float y) {
    u64 r; asm("mov.b64 %0, {%1,%2};" : "=l"(r) : "f"(x), "f"(y)); return r;
}
__device__ __forceinline__ void unpk(u64 v, float& x, float& y) {
    asm("mov.b64 {%0,%1}, %2;" : "=f"(x), "=f"(y) : "l"(v));
}
__device__ __forceinline__ u64 swp(u64 v) {
    u64 r;
    asm("{\n\t.reg .b32 lo, hi;\n\tmov.b64 {lo,hi}, %1;\n\tmov.b64 %0, {hi,lo};\n\t}"
        : "=l"(r) : "l"(v));
    return r;
}
__device__ __forceinline__ u64 ffma2(u64 a, u64 b, u64 c) {
    u64 d; asm("fma.rn.f32x2 %0, %1, %2, %3;" : "=l"(d) : "l"(a), "l"(b), "l"(c)); return d;
}
__device__ __forceinline__ u64 fmul2(u64 a, u64 b) {
    u64 d; asm("mul.rn.f32x2 %0, %1, %2;" : "=l"(d) : "l"(a), "l"(b)); return d;
}
__device__ __forceinline__ u64 fadd2(u64 a, u64 b) {
    u64 d; asm("add.rn.f32x2 %0, %1, %2;" : "=l"(d) : "l"(a), "l"(b)); return d;
}
__device__ __forceinline__ float2 cmulf(float2 a, float2 b) {
    return make_float2(a.x * b.x - a.y * b.y, a.x * b.y + a.y * b.x);
}

// ---- GF(2) helpers (precompute only) ----
__device__ __forceinline__ unsigned finv10(int type, unsigned idx) {
    int off = type ? (NQ / 2) : 1;
    unsigned y = idx;
    #pragma unroll
    for (int i = NQ - 1; i >= 0; --i) {
        int bc = NQ - 1 - i;
        int bt = NQ - 1 - ((i + off) % NQ);
        y ^= ((y >> bc) & 1u) << bt;
    }
    return y;
}
__device__ __forceinline__ unsigned gf2_mv(const unsigned* cols, unsigned x) {
    unsigned r = 0;
    #pragma unroll
    for (int i = 0; i < 5; ++i) if ((x >> i) & 1) r ^= cols[i];
    return r;
}
__device__ bool gf2_rank5(const unsigned* c) {
    unsigned m[5]; unsigned used = 0;
    #pragma unroll
    for (int i = 0; i < 5; ++i) m[i] = c[i];
    for (int bit = 0; bit < 5; ++bit) {
        int piv = -1;
        for (int i = 0; i < 5; ++i)
            if (!((used >> i) & 1) && ((m[i] >> bit) & 1)) { piv = i; break; }
        if (piv < 0) return false;
        used |= 1u << piv;
        for (int i = 0; i < 5; ++i)
            if (i != piv && ((m[i] >> bit) & 1)) m[i] ^= m[piv];
    }
    return true;
}
__device__ __forceinline__ void seed_to_A(int id, int p, unsigned* Ac) {
    unsigned seed = (unsigned)id * 0x9E3779B9u + (unsigned)p * 0x85EBCA6Bu + 0x6789u;
    #pragma unroll
    for (int i = 0; i < 5; ++i) {
        seed = seed * 1664525u + 1013904223u;
        Ac[i] = (seed >> 13) & 31u;
    }
}

__global__ void precompute_kernel(const float* __restrict__ w) {
    __shared__ int sel[2];
    __shared__ unsigned Acols[2][5];
    int t = threadIdx.x;
    if (t < 2) sel[t] = 0x7FFFFFFF;

    // fused variational gates
    if (t < NL * NQ) {
        int q = t % NQ;
        float w0 = w[t * 3 + 0], w1 = w[t * 3 + 1], w2 = w[t * 3 + 2];
        float sb, cb; sincosf(0.5f * w1, &sb, &cb);
        u64* g = g_gmat[t];
        if (q >= 1 && q <= 5) {
            // diagonalized lane-bit gate: RY real part + RZ phase scalars
            float s0, c0; sincosf(0.5f * w0, &s0, &c0);   // pre  = e^{-i w0/2}
            float s2, c2; sincosf(0.5f * w2, &s2, &c2);   // post = e^{-i w2/2}
            g[0] = pack2(cb, cb);      // cos pack
            g[1] = pack2(sb, sb);      // +sin pack  (own lane bit = 1)
            g[2] = pack2(-sb, -sb);    // -sin pack  (own lane bit = 0)
            g[3] = pack2(c0, -s0);     // pre0  scalar (b=0); b=1 -> conj
            g[4] = pack2(c2, -s2);     // post0 scalar (b=0); b=1 -> conj
            g[5] = 0; g[6] = 0; g[7] = 0;
        } else {
            float sp, cp; sincosf(0.5f * (w0 + w2), &sp, &cp);
            float sd, cd; sincosf(0.5f * (w0 - w2), &sd, &cd);
            float ar = cb * cp, ai = -cb * sp;   // U00
            float br = sb * cd, bi = -sb * sd;   // U10 ; U01=-conj(U10), U11=conj(U00)
            if (q == 0) {
                // merged-gather layout: {c00,d00,c01,d01, c11,d11,c10,d10}
                g[0] = pack2(ar, ar);   g[1] = pack2(-ai, ai);
                g[2] = pack2(-br, -br); g[3] = pack2(-bi, bi);
                g[4] = pack2(ar, ar);   g[5] = pack2(ai, -ai);
                g[6] = pack2(br, br);   g[7] = pack2(-bi, bi);
            } else {
                // standard layout: {c00,d00,c01,d01,c10,d10,c11,d11}
                g[0] = pack2(ar, ar);   g[1] = pack2(-ai, ai);
                g[2] = pack2(-br, -br); g[3] = pack2(-bi, bi);
                g[4] = pack2(br, br);   g[5] = pack2(-bi, bi);
                g[6] = pack2(ar, ar);   g[7] = pack2(ai, -ai);
            }
        }
    }
    __syncthreads();

    // search A per parity: store pass AND gather pass conflict-free
    {
        int p = t >> 6, tn = t & 63;
        unsigned Ph[5], Pl[5];
        #pragma unroll
        for (int i = 0; i < 5; ++i) {
            unsigned y = finv10(p, 1u << (4 + i));   // columns for j bits 4..8
            Ph[i] = y >> 5; Pl[i] = y & 31u;
        }
        for (int trial = 0; trial < 8; ++trial) {
            int id = tn * 8 + trial;
            unsigned Ac[5]; seed_to_A(id, p, Ac);
            unsigned B1[5] = {0x10u, Ac[0], Ac[1], Ac[2], Ac[3]};
            if (!gf2_rank5(B1)) continue;
            unsigned B2[5];
            #pragma unroll
            for (int i = 0; i < 5; ++i) B2[i] = Pl[i] ^ gf2_mv(Ac, Ph[i]);
            if (!gf2_rank5(B2)) continue;
            atomicMin(&sel[p], id);
        }
    }
    __syncthreads();
    if ((t & 63) == 0) {
        int p = t >> 6;
        unsigned Ac[5] = {0, 0, 0, 0, 0};
        if (sel[p] != 0x7FFFFFFF) seed_to_A(sel[p], p, Ac);
        #pragma unroll
        for (int i = 0; i < 5; ++i) Acols[p][i] = Ac[i];
    }
    __syncthreads();

    if (t < 64) {
        int p = t >> 5, v = t & 31;
        g_Amul[p][v] = gf2_mv(Acols[p], (unsigned)v);
    }
    // gather word-table: word for (W,lane,c) stored at W*256 + lane*8 + (c ^ (lane>>2))
    for (int i = t; i < 2 * 512; i += blockDim.x) {
        int p = i >> 9, widx = i & 511;
        int W = widx >> 8, lane = (widx >> 3) & 31, cs = widx & 7;
        int c = cs ^ (lane >> 2);
        unsigned j0 = (unsigned)(W * 512 + lane * 16 + 2 * c);
        unsigned e[2];
        #pragma unroll
        for (int h = 0; h < 2; ++h) {
            unsigned y = finv10(p, j0 + h);
            unsigned yh = y >> 5;
            unsigned addr = yh * 32 + ((y & 31u) ^ gf2_mv(Acols[p], yh));
            e[h] = addr | ((y >> 9) << 15);
        }
        g_T[p][widx] = e[0] | (e[1] << 16);
    }
}

// full-complex gate on k-bit mask M over 16 packed-complex amps
template<int M>
__device__ __forceinline__ void gate_reg(u64* r, const u64* __restrict__ C) {
    const u64 c00 = C[0], d00 = C[1], c01 = C[2], d01 = C[3];
    const u64 c10 = C[4], d10 = C[5], c11 = C[6], d11 = C[7];
    #pragma unroll
    for (int k = 0; k < 16; ++k) {
        if ((k & M) == 0) {
            const int k1 = k | M;
            u64 a0 = r[k], a1 = r[k1];
            u64 s0 = swp(a0), s1 = swp(a1);
            r[k]  = ffma2(c00, a0, ffma2(d00, s0, ffma2(c01, a1, fmul2(d01, s1))));
            r[k1] = ffma2(c10, a0, ffma2(d10, s0, ffma2(c11, a1, fmul2(d11, s1))));
        }
    }
}

// real RY butterfly on lane-bit xor distance D: r = c*own ± s*par
template<int D>
__device__ __forceinline__ void ry_shfl(u64* r, u64 cc, u64 ss) {
    #pragma unroll
    for (int k = 0; k < 16; ++k) {
        u64 own = r[k];
        u64 par = __shfl_xor_sync(0xffffffffu, own, D);
        r[k] = ffma2(ss, par, fmul2(cc, own));
    }
}

__global__ __launch_bounds__(TPB, 12) void qsim_kernel(
    const float* __restrict__ x,     // (B, 2*NQ)
    float* __restrict__ out)         // (B, NQ)
{
    __shared__ u64 sc[DIM];                    // 8 KB state scratch (A-swizzled)
    __shared__ u64 gmat_s[NL * NQ][8];         // 2.5 KB
    __shared__ unsigned Tp_s[2][512];          // 4 KB
    __shared__ float2 venc[NQ][2];
    __shared__ float red[2][NQ];

    const int t    = threadIdx.x;
    const int lane = t & 31;
    const int w    = t >> 5;                   // warp half = qubit-0 bit (j9)
    const int s    = blockIdx.x;
    const float inv_sqrt2 = 0.70710678118654752440f;
    const float pi_f      = 3.14159265358979323846f;

    // copy precomputed tables to smem
    {
        const u64* src = &g_gmat[0][0];
        u64* dst = &gmat_s[0][0];
        for (int i = t; i < NL * NQ * 8; i += TPB) dst[i] = src[i];
        const unsigned* ts = &g_T[0][0];
        unsigned* td = &Tp_s[0][0];
        for (int i = t; i < 1024; i += TPB) td[i] = ts[i];
    }
    // per-thread address constants from A tables
    const unsigned jhi = (unsigned)(w * 16 + (lane >> 1));
    const unsigned addrC0 = (jhi << 5) | (((unsigned)(lane & 1) << 4) ^ g_Amul[0][jhi]);
    const unsigned addrC1 = (jhi << 5) | (((unsigned)(lane & 1) << 4) ^ g_Amul[1][jhi]);
    const unsigned pc0 = 0x200u ^ g_Amul[0][16];
    const unsigned pc1 = 0x200u ^ g_Amul[1][16];

    if (t < NQ) {
        int q = t;
        float th = 0.5f * pi_f * (x[s * 2 * NQ + q]      + 1.0f);
        float ph = 0.5f * pi_f * (x[s * 2 * NQ + NQ + q] + 1.0f);
        float st, ct; sincosf(0.5f * th, &st, &ct);
        float sh, ch; sincosf(0.5f * ph, &sh, &ch);
        float a = inv_sqrt2 * (ct - st);
        float b = inv_sqrt2 * (ct + st);
        venc[q][0] = make_float2(a * ch, -a * sh);
        venc[q][1] = make_float2(b * ch,  b * sh);
    }
    __syncthreads();

    // ---- build product state: j = w*512 + lane*16 + k ; qubit q <-> j bit (9-q) ----
    u64 r[16];
    {
        float2 L = venc[0][w];
        L = cmulf(L, venc[1][(lane >> 4) & 1]);
        L = cmulf(L, venc[2][(lane >> 3) & 1]);
        L = cmulf(L, venc[3][(lane >> 2) & 1]);
        L = cmulf(L, venc[4][(lane >> 1) & 1]);
        L = cmulf(L, venc[5][lane & 1]);
        float2 RH[4], RL[4];
        #pragma unroll
        for (int h = 0; h < 4; ++h) RH[h] = cmulf(venc[6][(h >> 1) & 1], venc[7][h & 1]);
        #pragma unroll
        for (int l = 0; l < 4; ++l) RL[l] = cmulf(venc[8][(l >> 1) & 1], venc[9][l & 1]);
        #pragma unroll
        for (int k = 0; k < 16; ++k) {
            float2 a = cmulf(L, cmulf(RH[k >> 2], RL[k & 3]));
            r[k] = pack2(a.x, a.y);
        }
    }

    #pragma unroll 1
    for (int layer = 0; layer < NL; ++layer) {
        const u64 (*G)[8] = &gmat_s[layer * NQ];
        const int par = layer & 1;
        // qubits 6..9: full complex gates on k bits
        gate_reg<8>(r, G[6]);
        gate_reg<4>(r, G[7]);
        gate_reg<2>(r, G[8]);
        gate_reg<1>(r, G[9]);

        // ---- qubits 1..5 diagonalized: pre-phase, 5 real-RY butterflies, post-phase ----
        float2 pre = make_float2(1.0f, 0.0f), post = make_float2(1.0f, 0.0f);
        #pragma unroll
        for (int q = 1; q <= 5; ++q) {
            float px, py, ox, oy;
            unpk(G[q][3], px, py);
            unpk(G[q][4], ox, oy);
            if ((lane >> (5 - q)) & 1) { py = -py; oy = -oy; }
            pre  = cmulf(pre,  make_float2(px, py));
            post = cmulf(post, make_float2(ox, oy));
        }
        {
            const u64 Cp = pack2(pre.x, pre.x), Dp = pack2(-pre.y, pre.y);
            #pragma unroll
            for (int k = 0; k < 16; ++k)
                r[k] = ffma2(Cp, r[k], fmul2(Dp, swp(r[k])));
        }
        ry_shfl<16>(r, G[1][0], (lane & 16) ? G[1][1] : G[1][2]);
        ry_shfl<8>(r, G[2][0], (lane & 8)  ? G[2][1] : G[2][2]);
        ry_shfl<4>(r, G[3][0], (lane & 4)  ? G[3][1] : G[3][2]);
        ry_shfl<2>(r, G[4][0], (lane & 2)  ? G[4][1] : G[4][2]);
        ry_shfl<1>(r, G[5][0], (lane & 1)  ? G[5][1] : G[5][2]);
        {
            const u64 Cq = pack2(post.x, post.x), Dq = pack2(-post.y, post.y);
            #pragma unroll
            for (int k = 0; k < 16; ++k)
                r[k] = ffma2(Cq, r[k], fmul2(Dq, swp(r[k])));
        }

        // store state (A-swizzled, conflict-free)
        const unsigned addrC = par ? addrC1 : addrC0;
        #pragma unroll
        for (int k = 0; k < 16; ++k)
            sc[addrC ^ (unsigned)k] = r[k];
        __syncthreads();
        // gather = CNOT ring composed with full qubit-0 gate (conflict-free loads)
        const unsigned PC = par ? pc1 : pc0;
        const u64 q0_0 = G[0][0], q0_1 = G[0][1], q0_2 = G[0][2], q0_3 = G[0][3];
        const u64 q1_0 = G[0][4], q1_1 = G[0][5], q1_2 = G[0][6], q1_3 = G[0][7];
        const unsigned tbase = ((unsigned)w << 8) | ((unsigned)lane << 3);
        #pragma unroll
        for (int c = 0; c < 8; ++c) {
            unsigned tw = Tp_s[par][tbase | ((unsigned)c ^ (unsigned)(lane >> 2))];
            #pragma unroll
            for (int h = 0; h < 2; ++h) {
                unsigned e = (h == 0) ? (tw & 0xffffu) : (tw >> 16);
                unsigned idx = e & 1023u;
                bool bb = (e >> 15) != 0;
                u64 a = sc[idx];
                u64 p = sc[idx ^ PC];
                u64 cA = bb ? q1_0 : q0_0;
                u64 dA = bb ? q1_1 : q0_1;
                u64 cB = bb ? q1_2 : q0_2;
                u64 dB = bb ? q1_3 : q0_3;
                r[2 * c + h] = ffma2(cA, a, ffma2(dA, swp(a), ffma2(cB, p, fmul2(dB, swp(p)))));
            }
        }
        __syncthreads();
    }

    // ---- <Z_q> readout ----
    u64 tot = 0, accP[4] = {0,0,0,0}, accN[4] = {0,0,0,0};
    #pragma unroll
    for (int k = 0; k < 16; ++k) {
        u64 sq = fmul2(r[k], r[k]);          // (re^2, im^2)
        tot = fadd2(tot, sq);
        #pragma unroll
        for (int b = 0; b < 4; ++b) {
            if ((k >> b) & 1) accN[b] = fadd2(accN[b], sq);
            else              accP[b] = fadd2(accP[b], sq);
        }
    }
    float zq[NQ];
    {
        float tl, th; unpk(tot, tl, th);
        float pr_tot = tl + th;
        zq[0] = w ? -pr_tot : pr_tot;
        zq[1] = (lane & 16) ? -pr_tot : pr_tot;
        zq[2] = (lane & 8)  ? -pr_tot : pr_tot;
        zq[3] = (lane & 4)  ? -pr_tot : pr_tot;
        zq[4] = (lane & 2)  ? -pr_tot : pr_tot;
        zq[5] = (lane & 1)  ? -pr_tot : pr_tot;
        #pragma unroll
        for (int b = 0; b < 4; ++b) {        // k bit b <-> qubit 9-b
            float pl, ph, nl, nh;
            unpk(accP[b], pl, ph); unpk(accN[b], nl, nh);
            zq[9 - b] = (pl + ph) - (nl + nh);
        }
    }
    #pragma unroll
    for (int q = 0; q < NQ; ++q) {
        #pragma unroll
        for (int o = 16; o > 0; o >>= 1)
            zq[q] += __shfl_xor_sync(0xffffffffu, zq[q], o);
    }
    if (lane == 0) {
        #pragma unroll
        for (int q = 0; q < NQ; ++q) red[w][q] = zq[q];
    }
    __syncthreads();
    if (t < NQ)
        out[s * NQ + t] = red[0][t] + red[1][t];
}

extern "C" void kernel_launch(void* const* d_in, const int* in_sizes, int n_in,
                              void* d_out, int out_size) {
    const float* x = (const float*)d_in[0];
    const float* w = (const float*)d_in[1];
    float* out = (float*)d_out;
    int B = in_sizes[0] / (2 * NQ);   // 4096 flattened samples
    precompute_kernel<<<1, 128>>>(w);
    qsim_kernel<<<B, TPB>>>(x, out);
}

// round 9
// speedup vs baseline: 1.9020x; 1.2750x over previous
#include <cuda_runtime.h>

#define NQ  10
#define DIM 1024
#define NL  4
#define TPB 64

typedef unsigned long long u64;

// Hardcoded GF(2) swizzle matrices (derived analytically from the fixed CNOT rings;
// satisfy rank-5 store & gather conflict-freedom constraints for each layer parity).
#define A0_0 1u
#define A0_1 2u
#define A0_2 4u
#define A0_3 9u
#define A0_4 0u
#define A1_0 2u
#define A1_1 4u
#define A1_2 8u
#define A1_3 0x11u
#define A1_4 1u
#define PC0  0x200u          // 0x200 ^ A0_4
#define PC1  0x201u          // 0x200 ^ A1_4

__device__ u64 g_gmat[NL * NQ][8];       // packed gate coefficients
__device__ unsigned g_T[2][512];         // gather word-table (conflict-free layout)

__device__ __forceinline__ unsigned amul(int p, unsigned v) {
    unsigned r = 0;
    if (p == 0) {
        if (v & 1u)  r ^= A0_0;
        if (v & 2u)  r ^= A0_1;
        if (v & 4u)  r ^= A0_2;
        if (v & 8u)  r ^= A0_3;
        if (v & 16u) r ^= A0_4;
    } else {
        if (v & 1u)  r ^= A1_0;
        if (v & 2u)  r ^= A1_1;
        if (v & 4u)  r ^= A1_2;
        if (v & 8u)  r ^= A1_3;
        if (v & 16u) r ^= A1_4;
    }
    return r;
}

__device__ __forceinline__ u64 pack2(float x, float y) {
    u64 r; asm("mov.b64 %0, {%1,%2};" : "=l"(r) : "f"(x), "f"(y)); return r;
}
__device__ __forceinline__ void unpk(u64 v, float& x, float& y) {
    asm("mov.b64 {%0,%1}, %2;" : "=f"(x), "=f"(y) : "l"(v));
}
__device__ __forceinline__ u64 swp(u64 v) {
    u64 r;
    asm("{\n\t.reg .b32 lo, hi;\n\tmov.b64 {lo,hi}, %1;\n\tmov.b64 %0, {hi,lo};\n\t}"
        : "=l"(r) : "l"(v));
    return r;
}
__device__ __forceinline__ u64 ffma2(u64 a, u64 b, u64 c) {
    u64 d; asm("fma.rn.f32x2 %0, %1, %2, %3;" : "=l"(d) : "l"(a), "l"(b), "l"(c)); return d;
}
__device__ __forceinline__ u64 fmul2(u64 a, u64 b) {
    u64 d; asm("mul.rn.f32x2 %0, %1, %2;" : "=l"(d) : "l"(a), "l"(b)); return d;
}
__device__ __forceinline__ u64 fadd2(u64 a, u64 b) {
    u64 d; asm("add.rn.f32x2 %0, %1, %2;" : "=l"(d) : "l"(a), "l"(b)); return d;
}
__device__ __forceinline__ float2 cmulf(float2 a, float2 b) {
    return make_float2(a.x * b.x - a.y * b.y, a.x * b.y + a.y * b.x);
}

__device__ __forceinline__ unsigned finv10(int type, unsigned idx) {
    int off = type ? (NQ / 2) : 1;
    unsigned y = idx;
    #pragma unroll
    for (int i = NQ - 1; i >= 0; --i) {
        int bc = NQ - 1 - i;
        int bt = NQ - 1 - ((i + off) % NQ);
        y ^= ((y >> bc) & 1u) << bt;
    }
    return y;
}

__global__ void precompute_kernel(const float* __restrict__ w) {
    int t = threadIdx.x;

    // fused variational gates
    if (t < NL * NQ) {
        int q = t % NQ;
        float w0 = w[t * 3 + 0], w1 = w[t * 3 + 1], w2 = w[t * 3 + 2];
        float sb, cb; sincosf(0.5f * w1, &sb, &cb);
        u64* g = g_gmat[t];
        if (q >= 1 && q <= 5) {
            // diagonalized lane-bit gate: RY real part + RZ phase scalars
            float s0, c0; sincosf(0.5f * w0, &s0, &c0);   // pre  = e^{-i w0/2}
            float s2, c2; sincosf(0.5f * w2, &s2, &c2);   // post = e^{-i w2/2}
            g[0] = pack2(cb, cb);
            g[1] = pack2(sb, sb);
            g[2] = pack2(-sb, -sb);
            g[3] = pack2(c0, -s0);
            g[4] = pack2(c2, -s2);
            g[5] = 0; g[6] = 0; g[7] = 0;
        } else {
            float sp, cp; sincosf(0.5f * (w0 + w2), &sp, &cp);
            float sd, cd; sincosf(0.5f * (w0 - w2), &sd, &cd);
            float ar = cb * cp, ai = -cb * sp;   // U00
            float br = sb * cd, bi = -sb * sd;   // U10 ; U01=-conj(U10), U11=conj(U00)
            if (q == 0) {
                // merged-gather layout: {c00,d00,c01,d01, c11,d11,c10,d10}
                g[0] = pack2(ar, ar);   g[1] = pack2(-ai, ai);
                g[2] = pack2(-br, -br); g[3] = pack2(-bi, bi);
                g[4] = pack2(ar, ar);   g[5] = pack2(ai, -ai);
                g[6] = pack2(br, br);   g[7] = pack2(-bi, bi);
            } else {
                // standard layout: {c00,d00,c01,d01,c10,d10,c11,d11}
                g[0] = pack2(ar, ar);   g[1] = pack2(-ai, ai);
                g[2] = pack2(-br, -br); g[3] = pack2(-bi, bi);
                g[4] = pack2(br, br);   g[5] = pack2(-bi, bi);
                g[6] = pack2(ar, ar);   g[7] = pack2(ai, -ai);
            }
        }
    }

    // gather word-table: word for (W,lane,c) stored at W*256 + lane*8 + (c ^ (lane>>2))
    for (int i = t; i < 2 * 512; i += blockDim.x) {
        int p = i >> 9, widx = i & 511;
        int W = widx >> 8, lane = (widx >> 3) & 31, cs = widx & 7;
        int c = cs ^ (lane >> 2);
        unsigned j0 = (unsigned)(W * 512 + lane * 16 + 2 * c);
        unsigned e[2];
        #pragma unroll
        for (int h = 0; h < 2; ++h) {
            unsigned y = finv10(p, j0 + h);
            unsigned yh = y >> 5;
            unsigned addr = yh * 32 + ((y & 31u) ^ amul(p, yh));
            e[h] = addr | ((y >> 9) << 15);
        }
        g_T[p][widx] = e[0] | (e[1] << 16);
    }
}

// full-complex gate on k-bit mask M over 16 packed-complex amps
template<int M>
__device__ __forceinline__ void gate_reg(u64* r, const u64* __restrict__ C) {
    const u64 c00 = C[0], d00 = C[1], c01 = C[2], d01 = C[3];
    const u64 c10 = C[4], d10 = C[5], c11 = C[6], d11 = C[7];
    #pragma unroll
    for (int k = 0; k < 16; ++k) {
        if ((k & M) == 0) {
            const int k1 = k | M;
            u64 a0 = r[k], a1 = r[k1];
            u64 s0 = swp(a0), s1 = swp(a1);
            r[k]  = ffma2(c00, a0, ffma2(d00, s0, ffma2(c01, a1, fmul2(d01, s1))));
            r[k1] = ffma2(c10, a0, ffma2(d10, s0, ffma2(c11, a1, fmul2(d11, s1))));
        }
    }
}

// real RY butterfly on lane-bit xor distance D: r = c*own ± s*par
template<int D>
__device__ __forceinline__ void ry_shfl(u64* r, u64 cc, u64 ss) {
    #pragma unroll
    for (int k = 0; k < 16; ++k) {
        u64 own = r[k];
        u64 par = __shfl_xor_sync(0xffffffffu, own, D);
        r[k] = ffma2(ss, par, fmul2(cc, own));
    }
}

__global__ __launch_bounds__(TPB, 12) void qsim_kernel(
    const float* __restrict__ x,     // (B, 2*NQ)
    float* __restrict__ out)         // (B, NQ)
{
    __shared__ u64 sc[DIM];                    // 8 KB state scratch (A-swizzled)
    __shared__ u64 gmat_s[NL * NQ][8];         // 2.5 KB
    __shared__ unsigned Tp_s[2][512];          // 4 KB
    __shared__ float2 venc[NQ][2];
    __shared__ float red[2][NQ];

    const int t    = threadIdx.x;
    const int lane = t & 31;
    const int w    = t >> 5;                   // warp half = qubit-0 bit (j9)
    const int s    = blockIdx.x;
    const float inv_sqrt2 = 0.70710678118654752440f;
    const float pi_f      = 3.14159265358979323846f;

    // copy precomputed tables to smem
    {
        const u64* src = &g_gmat[0][0];
        u64* dst = &gmat_s[0][0];
        for (int i = t; i < NL * NQ * 8; i += TPB) dst[i] = src[i];
        const unsigned* ts = &g_T[0][0];
        unsigned* td = &Tp_s[0][0];
        for (int i = t; i < 1024; i += TPB) td[i] = ts[i];
    }
    // per-thread address constants (A hardcoded)
    const unsigned jhi = (unsigned)(w * 16 + (lane >> 1));
    const unsigned addrC0 = (jhi << 5) | (((unsigned)(lane & 1) << 4) ^ amul(0, jhi));
    const unsigned addrC1 = (jhi << 5) | (((unsigned)(lane & 1) << 4) ^ amul(1, jhi));

    if (t < NQ) {
        int q = t;
        float th = 0.5f * pi_f * (x[s * 2 * NQ + q]      + 1.0f);
        float ph = 0.5f * pi_f * (x[s * 2 * NQ + NQ + q] + 1.0f);
        float st, ct; sincosf(0.5f * th, &st, &ct);
        float sh, ch; sincosf(0.5f * ph, &sh, &ch);
        float a = inv_sqrt2 * (ct - st);
        float b = inv_sqrt2 * (ct + st);
        venc[q][0] = make_float2(a * ch, -a * sh);
        venc[q][1] = make_float2(b * ch,  b * sh);
    }
    __syncthreads();

    // ---- build product state: j = w*512 + lane*16 + k ; qubit q <-> j bit (9-q) ----
    u64 r[16];
    {
        float2 L = venc[0][w];
        L = cmulf(L, venc[1][(lane >> 4) & 1]);
        L = cmulf(L, venc[2][(lane >> 3) & 1]);
        L = cmulf(L, venc[3][(lane >> 2) & 1]);
        L = cmulf(L, venc[4][(lane >> 1) & 1]);
        L = cmulf(L, venc[5][lane & 1]);
        float2 RH[4], RL[4];
        #pragma unroll
        for (int h = 0; h < 4; ++h) RH[h] = cmulf(venc[6][(h >> 1) & 1], venc[7][h & 1]);
        #pragma unroll
        for (int l = 0; l < 4; ++l) RL[l] = cmulf(venc[8][(l >> 1) & 1], venc[9][l & 1]);
        #pragma unroll
        for (int k = 0; k < 16; ++k) {
            float2 a = cmulf(L, cmulf(RH[k >> 2], RL[k & 3]));
            r[k] = pack2(a.x, a.y);
        }
    }

    #pragma unroll 1
    for (int layer = 0; layer < NL; ++layer) {
        const u64 (*G)[8] = &gmat_s[layer * NQ];
        const int par = layer & 1;
        // qubits 6..9: full complex gates on k bits
        gate_reg<8>(r, G[6]);
        gate_reg<4>(r, G[7]);
        gate_reg<2>(r, G[8]);
        gate_reg<1>(r, G[9]);

        // ---- qubits 1..5 diagonalized: pre-phase, 5 real-RY butterflies, post-phase ----
        float2 pre = make_float2(1.0f, 0.0f), post = make_float2(1.0f, 0.0f);
        #pragma unroll
        for (int q = 1; q <= 5; ++q) {
            float px, py, ox, oy;
            unpk(G[q][3], px, py);
            unpk(G[q][4], ox, oy);
            if ((lane >> (5 - q)) & 1) { py = -py; oy = -oy; }
            pre  = cmulf(pre,  make_float2(px, py));
            post = cmulf(post, make_float2(ox, oy));
        }
        {
            const u64 Cp = pack2(pre.x, pre.x), Dp = pack2(-pre.y, pre.y);
            #pragma unroll
            for (int k = 0; k < 16; ++k)
                r[k] = ffma2(Cp, r[k], fmul2(Dp, swp(r[k])));
        }
        ry_shfl<16>(r, G[1][0], (lane & 16) ? G[1][1] : G[1][2]);
        ry_shfl<8>(r, G[2][0], (lane & 8)  ? G[2][1] : G[2][2]);
        ry_shfl<4>(r, G[3][0], (lane & 4)  ? G[3][1] : G[3][2]);
        ry_shfl<2>(r, G[4][0], (lane & 2)  ? G[4][1] : G[4][2]);
        ry_shfl<1>(r, G[5][0], (lane & 1)  ? G[5][1] : G[5][2]);
        {
            const u64 Cq = pack2(post.x, post.x), Dq = pack2(-post.y, post.y);
            #pragma unroll
            for (int k = 0; k < 16; ++k)
                r[k] = ffma2(Cq, r[k], fmul2(Dq, swp(r[k])));
        }

        // store state (A-swizzled, conflict-free)
        const unsigned addrC = par ? addrC1 : addrC0;
        #pragma unroll
        for (int k = 0; k < 16; ++k)
            sc[addrC ^ (unsigned)k] = r[k];
        __syncthreads();
        // gather = CNOT ring composed with full qubit-0 gate (conflict-free loads)
        const unsigned PC = par ? PC1 : PC0;
        const u64 q0_0 = G[0][0], q0_1 = G[0][1], q0_2 = G[0][2], q0_3 = G[0][3];
        const u64 q1_0 = G[0][4], q1_1 = G[0][5], q1_2 = G[0][6], q1_3 = G[0][7];
        const unsigned tbase = ((unsigned)w << 8) | ((unsigned)lane << 3);
        #pragma unroll
        for (int c = 0; c < 8; ++c) {
            unsigned tw = Tp_s[par][tbase | ((unsigned)c ^ (unsigned)(lane >> 2))];
            #pragma unroll
            for (int h = 0; h < 2; ++h) {
                unsigned e = (h == 0) ? (tw & 0xffffu) : (tw >> 16);
                unsigned idx = e & 1023u;
                bool bb = (e >> 15) != 0;
                u64 a = sc[idx];
                u64 p = sc[idx ^ PC];
                u64 cA = bb ? q1_0 : q0_0;
                u64 dA = bb ? q1_1 : q0_1;
                u64 cB = bb ? q1_2 : q0_2;
                u64 dB = bb ? q1_3 : q0_3;
                r[2 * c + h] = ffma2(cA, a, ffma2(dA, swp(a), ffma2(cB, p, fmul2(dB, swp(p)))));
            }
        }
        __syncthreads();
    }

    // ---- <Z_q> readout ----
    u64 tot = 0, accP[4] = {0,0,0,0}, accN[4] = {0,0,0,0};
    #pragma unroll
    for (int k = 0; k < 16; ++k) {
        u64 sq = fmul2(r[k], r[k]);          // (re^2, im^2)
        tot = fadd2(tot, sq);
        #pragma unroll
        for (int b = 0; b < 4; ++b) {
            if ((k >> b) & 1) accN[b] = fadd2(accN[b], sq);
            else              accP[b] = fadd2(accP[b], sq);
        }
    }
    float zq[NQ];
    {
        float tl, th; unpk(tot, tl, th);
        float pr_tot = tl + th;
        zq[0] = w ? -pr_tot : pr_tot;
        zq[1] = (lane & 16) ? -pr_tot : pr_tot;
        zq[2] = (lane & 8)  ? -pr_tot : pr_tot;
        zq[3] = (lane & 4)  ? -pr_tot : pr_tot;
        zq[4] = (lane & 2)  ? -pr_tot : pr_tot;
        zq[5] = (lane & 1)  ? -pr_tot : pr_tot;
        #pragma unroll
        for (int b = 0; b < 4; ++b) {        // k bit b <-> qubit 9-b
            float pl, ph, nl, nh;
            unpk(accP[b], pl, ph); unpk(accN[b], nl, nh);
            zq[9 - b] = (pl + ph) - (nl + nh);
        }
    }
    #pragma unroll
    for (int q = 0; q < NQ; ++q) {
        #pragma unroll
        for (int o = 16; o > 0; o >>= 1)
            zq[q] += __shfl_xor_sync(0xffffffffu, zq[q], o);
    }
    if (lane == 0) {
        #pragma unroll
        for (int q = 0; q < NQ; ++q) red[w][q] = zq[q];
    }
    __syncthreads();
    if (t < NQ)
        out[s * NQ + t] = red[0][t] + red[1][t];
}

extern "C" void kernel_launch(void* const* d_in, const int* in_sizes, int n_in,
                              void* d_out, int out_size) {
    const float* x = (const float*)d_in[0];
    const float* w = (const float*)d_in[1];
    float* out = (float*)d_out;
    int B = in_sizes[0] / (2 * NQ);   // 4096 flattened samples
    precompute_kernel<<<1, 128>>>(w);
    qsim_kernel<<<B, TPB>>>(x, out);
}